// round 3
// baseline (speedup 1.0000x reference)
#include <cuda_runtime.h>
#include <cuda_bf16.h>
#include <cstdint>

// ---------------------------------------------------------------------------
// Problem: LSTM, batch=64, seq=512, input=512, hidden=512, fp32.
// Inputs (metadata order): x [64,512,512], weight_ih [2048,512],
// weight_hh [2048,512], bias_ih [2048], bias_hh [2048].
// Output (flattened tuple): hidden_seq [64,512,512], h_f [64,512], c_f [64,512]
// ---------------------------------------------------------------------------

#define BATCH 64
#define SEQ   512
#define ISZ   512
#define HS    512
#define GATES (4 * HS)   // 2048

// Scratch: x_proj in (s, b, 4H) layout, and cell state c.
__device__ float g_xproj[(size_t)SEQ * BATCH * GATES];   // 256 MB
__device__ float g_c[BATCH * HS];                        // 128 KB

// ===========================================================================
// Kernel 1: x_proj[s][b][n] = sum_k x[b][s][k] * W_ih[n][k] + bias_ih[n] + bias_hh[n]
// Standard 128x128x8 fp32 SGEMM, TM=TN=8, 256 threads.
// M = 32768 (m = b*512+s), N = 2048, K = 512.
// ===========================================================================
#define GBM 128
#define GBN 128
#define GBK 8

__global__ __launch_bounds__(256, 2)
void xproj_gemm_kernel(const float* __restrict__ x,
                       const float* __restrict__ wih,
                       const float* __restrict__ bih,
                       const float* __restrict__ bhh)
{
    __shared__ float As[GBK][GBM];
    __shared__ float Bs[GBK][GBN];

    const int tid = threadIdx.x;
    const int m0 = blockIdx.y * GBM;
    const int n0 = blockIdx.x * GBN;

    // Loaders: 128 rows x 8 k = 256 float4 per tile (one per thread).
    const int lrow = tid >> 1;           // 0..127
    const int lk4  = (tid & 1) * 4;      // 0 or 4

    const int tx = tid & 15;             // 0..15 -> n block of 8
    const int ty = tid >> 4;             // 0..15 -> m block of 8

    float acc[8][8];
#pragma unroll
    for (int i = 0; i < 8; i++)
#pragma unroll
        for (int j = 0; j < 8; j++) acc[i][j] = 0.f;

    const float* Aptr = x   + (size_t)(m0 + lrow) * ISZ + lk4;
    const float* Bptr = wih + (size_t)(n0 + lrow) * ISZ + lk4;

    float4 pa = *(const float4*)Aptr;
    float4 pb = *(const float4*)Bptr;

    const int NT = ISZ / GBK;  // 64 k-tiles
    for (int t = 0; t < NT; t++) {
        // store staged tile (transposed)
        As[lk4 + 0][lrow] = pa.x; As[lk4 + 1][lrow] = pa.y;
        As[lk4 + 2][lrow] = pa.z; As[lk4 + 3][lrow] = pa.w;
        Bs[lk4 + 0][lrow] = pb.x; Bs[lk4 + 1][lrow] = pb.y;
        Bs[lk4 + 2][lrow] = pb.z; Bs[lk4 + 3][lrow] = pb.w;
        __syncthreads();

        if (t + 1 < NT) {
            pa = *(const float4*)(Aptr + (t + 1) * GBK);
            pb = *(const float4*)(Bptr + (t + 1) * GBK);
        }

#pragma unroll
        for (int kk = 0; kk < GBK; kk++) {
            float a[8], b[8];
#pragma unroll
            for (int i = 0; i < 8; i++) a[i] = As[kk][ty * 8 + i];
#pragma unroll
            for (int j = 0; j < 8; j++) b[j] = Bs[kk][tx * 8 + j];
#pragma unroll
            for (int i = 0; i < 8; i++)
#pragma unroll
                for (int j = 0; j < 8; j++) acc[i][j] += a[i] * b[j];
        }
        __syncthreads();
    }

    // bias and write-out to (s, b, n) layout
    float bsum[8];
#pragma unroll
    for (int j = 0; j < 8; j++) {
        int n = n0 + tx * 8 + j;
        bsum[j] = bih[n] + bhh[n];
    }

#pragma unroll
    for (int i = 0; i < 8; i++) {
        int m = m0 + ty * 8 + i;
        int b = m >> 9;       // m / 512
        int s = m & 511;      // m % 512
        float* orow = g_xproj + ((size_t)s * BATCH + b) * GATES + n0 + tx * 8;
#pragma unroll
        for (int j = 0; j < 8; j += 4) {
            float4 v;
            v.x = acc[i][j + 0] + bsum[j + 0];
            v.y = acc[i][j + 1] + bsum[j + 1];
            v.z = acc[i][j + 2] + bsum[j + 2];
            v.w = acc[i][j + 3] + bsum[j + 3];
            *(float4*)(orow + j) = v;
        }
    }
}

// ===========================================================================
// Kernel 2: one LSTM timestep.
// gates[b][g*512+j] = xproj[s][b][g*512+j] + sum_k h_prev[b][k]*W_hh[g*512+j][k]
// Grid: 128 blocks, block owns 4 hidden units j (all 4 gates) x all 64 batches.
// 256 threads = 4 b-groups x 16 k-slices x 4 j-lanes.
// Each thread: 16 batches register-tiled, 32 k values.
// ===========================================================================
#define WSTR 520   // padded row stride for W_s (16 rows)
#define HSTR 516   // padded row stride for h_s (64 rows)
#define SM_W_FLOATS  (16 * WSTR)            // 8320
#define SM_H_FLOATS  (64 * HSTR)            // 33024
#define SM_RED_FLOATS (8 * 4 * 16 * 4)      // 2048
#define STEP_SMEM_BYTES ((SM_W_FLOATS + SM_H_FLOATS + SM_RED_FLOATS) * 4)

__device__ __forceinline__ float fsigmoid(float x) {
    return 1.f / (1.f + __expf(-x));
}
__device__ __forceinline__ float ftanh_fast(float x) {
    // tanh(x) = 2*sigmoid(2x) - 1
    return 2.f / (1.f + __expf(-2.f * x)) - 1.f;
}

__global__ __launch_bounds__(256, 1)
void lstm_step_kernel(const float* __restrict__ whh,
                      float* __restrict__ out,       // hidden_seq (b, s, j)
                      int s,
                      float* __restrict__ hf_out,    // may be null
                      float* __restrict__ cf_out)    // may be null
{
    extern __shared__ float sm[];
    float* W_s = sm;                       // [16][WSTR]
    float* h_s = sm + SM_W_FLOATS;         // [64][HSTR]
    float* red = h_s + SM_H_FLOATS;        // [warp][jl][bi][g]

    const int tid = threadIdx.x;
    const int j0 = blockIdx.x * 4;

    // ---- stage W rows: (g*512 + j0 + jl) for g=0..3, jl=0..3 ----
    for (int t = tid; t < 16 * 128; t += 256) {
        int row = t >> 7;            // 0..15
        int kq = (t & 127) << 2;     // 0..508 step 4
        int g = row >> 2, jl = row & 3;
        float4 v = *(const float4*)(whh + (size_t)(g * HS + j0 + jl) * HS + kq);
        *(float4*)&W_s[row * WSTR + kq] = v;
    }

    // ---- stage h_prev (zeros at s==0, else read previous output row) ----
    if (s == 0) {
        float4 z = make_float4(0.f, 0.f, 0.f, 0.f);
        for (int t = tid; t < 64 * 128; t += 256) {
            int b = t >> 7;
            int kq = (t & 127) << 2;
            *(float4*)&h_s[b * HSTR + kq] = z;
        }
    } else {
        for (int t = tid; t < 64 * 128; t += 256) {
            int b = t >> 7;
            int kq = (t & 127) << 2;
            float4 v = *(const float4*)(out + ((size_t)b * SEQ + (s - 1)) * HS + kq);
            *(float4*)&h_s[b * HSTR + kq] = v;
        }
    }
    __syncthreads();

    // ---- main dot-products ----
    const int jl   = tid & 3;
    const int ksub = (tid >> 2) & 15;
    const int bg   = tid >> 6;

    float acc[16][4];
#pragma unroll
    for (int bi = 0; bi < 16; bi++)
#pragma unroll
        for (int g = 0; g < 4; g++) acc[bi][g] = 0.f;

    const float* Wb = W_s + jl * WSTR;
    const float* Hb = h_s + (bg * 16) * HSTR;

#pragma unroll 4
    for (int r = 0; r < 32; r++) {
        int k = ksub + (r << 4);
        float w0 = Wb[0 * 4 * WSTR + k];
        float w1 = Wb[1 * 4 * WSTR + k];
        float w2 = Wb[2 * 4 * WSTR + k];
        float w3 = Wb[3 * 4 * WSTR + k];
#pragma unroll
        for (int bi = 0; bi < 16; bi++) {
            float hv = Hb[bi * HSTR + k];
            acc[bi][0] += hv * w0;
            acc[bi][1] += hv * w1;
            acc[bi][2] += hv * w2;
            acc[bi][3] += hv * w3;
        }
    }

    // ---- reduce over ksub: butterfly within warp (8 ksub, lane stride 4) ----
#pragma unroll
    for (int off = 4; off <= 16; off <<= 1) {
#pragma unroll
        for (int bi = 0; bi < 16; bi++)
#pragma unroll
            for (int g = 0; g < 4; g++)
                acc[bi][g] += __shfl_xor_sync(0xffffffffu, acc[bi][g], off);
    }

    // representative lanes (lane 0..3 == jl) write warp partials to smem
    const int warp = tid >> 5;
    const int lane = tid & 31;
    if (lane < 4) {
#pragma unroll
        for (int bi = 0; bi < 16; bi++)
#pragma unroll
            for (int g = 0; g < 4; g++)
                red[((warp * 4 + lane) * 16 + bi) * 4 + g] = acc[bi][g];
    }
    __syncthreads();

    // ---- cell update: 256 (b, j) pairs, one per thread ----
    {
        const int b   = tid >> 2;
        const int jl2 = tid & 3;
        const int j   = j0 + jl2;
        const int bg2 = b >> 4;
        const int bi2 = b & 15;

        float gate[4];
#pragma unroll
        for (int g = 0; g < 4; g++) {
            gate[g] = red[(((bg2 * 2 + 0) * 4 + jl2) * 16 + bi2) * 4 + g]
                    + red[(((bg2 * 2 + 1) * 4 + jl2) * 16 + bi2) * 4 + g];
        }

        const float* xp = g_xproj + ((size_t)s * BATCH + b) * GATES;
        float gi = gate[0] + xp[0 * HS + j];
        float gf = gate[1] + xp[1 * HS + j];
        float gc = gate[2] + xp[2 * HS + j];
        float go = gate[3] + xp[3 * HS + j];

        float i_ = fsigmoid(gi);
        float f_ = fsigmoid(gf);
        float c_in = ftanh_fast(gc);
        float o_ = fsigmoid(go);

        float cp = (s == 0) ? 0.f : g_c[b * HS + j];
        float cn = f_ * cp + i_ * c_in;
        float hn = o_ * ftanh_fast(cn);

        g_c[b * HS + j] = cn;
        out[((size_t)b * SEQ + s) * HS + j] = hn;
        if (s == SEQ - 1 && hf_out != nullptr) {
            hf_out[b * HS + j] = hn;
            cf_out[b * HS + j] = cn;
        }
    }
}

// ===========================================================================
// Launch
// ===========================================================================
extern "C" void kernel_launch(void* const* d_in, const int* in_sizes, int n_in,
                              void* d_out, int out_size)
{
    const float* x   = (const float*)d_in[0];
    const float* wih = (const float*)d_in[1];
    const float* whh = (const float*)d_in[2];
    const float* bih = (const float*)d_in[3];
    const float* bhh = (const float*)d_in[4];

    float* out = (float*)d_out;

    const size_t hidden_elems = (size_t)BATCH * SEQ * HS;   // 16,777,216
    float* hf = nullptr;
    float* cf = nullptr;
    if ((size_t)out_size >= hidden_elems + 2 * (size_t)BATCH * HS) {
        hf = out + hidden_elems;
        cf = hf + (size_t)BATCH * HS;
    }

    // allow >48KB dynamic smem for the step kernel (idempotent host call)
    cudaFuncSetAttribute(lstm_step_kernel,
                         cudaFuncAttributeMaxDynamicSharedMemorySize,
                         STEP_SMEM_BYTES);

    // Phase 1: input projection GEMM
    dim3 ggrid(GATES / GBN, (BATCH * SEQ) / GBM);   // (16, 256)
    xproj_gemm_kernel<<<ggrid, 256>>>(x, wih, bih, bhh);

    // Phase 2: sequential recurrence, one kernel per timestep
    for (int s = 0; s < SEQ; s++) {
        lstm_step_kernel<<<HS / 4, 256, STEP_SMEM_BYTES>>>(whh, out, s, hf, cf);
    }
}

// round 5
// speedup vs baseline: 1.3971x; 1.3971x over previous
#include <cuda_runtime.h>
#include <cuda_bf16.h>
#include <cstdint>

// ---------------------------------------------------------------------------
// LSTM: batch=64, seq=512, input=512, hidden=512, fp32.
// Inputs: x [64,512,512], weight_ih [2048,512], weight_hh [2048,512],
//         bias_ih [2048], bias_hh [2048].
// Output: hidden_seq [64,512,512], h_f [64,512], c_f [64,512].
// ---------------------------------------------------------------------------

#define BATCH 64
#define SEQ   512
#define ISZ   512
#define HS    512
#define GATES (4 * HS)   // 2048

__device__ float g_xproj[(size_t)SEQ * BATCH * GATES];   // 256 MB scratch
__device__ float g_h[2][HS][BATCH];                      // transposed h, double buffer
__device__ unsigned g_count;                             // grid barrier arrivals (monotonic)
__device__ unsigned g_release;                           // grid barrier epoch

// ---------------- packed f32x2 helpers ----------------
__device__ __forceinline__ unsigned long long bcast2(float x) {
    unsigned long long r; unsigned u = __float_as_uint(x);
    asm("mov.b64 %0, {%1, %1};" : "=l"(r) : "r"(u));
    return r;
}
__device__ __forceinline__ void fma2(unsigned long long &acc,
                                     unsigned long long a, unsigned long long b) {
    asm("fma.rn.f32x2 %0, %1, %2, %0;" : "+l"(acc) : "l"(a), "l"(b));
}
__device__ __forceinline__ float2 unpack2(unsigned long long v) {
    unsigned lo, hi;
    asm("mov.b64 {%0, %1}, %2;" : "=r"(lo), "=r"(hi) : "l"(v));
    return make_float2(__uint_as_float(lo), __uint_as_float(hi));
}

// ===========================================================================
// Kernel 0: reset barrier state (runs on every graph replay, before persistent)
// ===========================================================================
__global__ void init_barrier_kernel() {
    g_count = 0u;
    g_release = 0u;
}

// ===========================================================================
// Kernel 1: x_proj GEMM, 128x128x8 tile, f32x2 packed math.
// x_proj[s][b][n] = sum_k x[b][s][k]*W_ih[n][k] + bias_ih[n] + bias_hh[n]
// ===========================================================================
#define GBM 128
#define GBN 128
#define GBK 8

__global__ __launch_bounds__(256, 2)
void xproj_gemm_kernel(const float* __restrict__ x,
                       const float* __restrict__ wih,
                       const float* __restrict__ bih,
                       const float* __restrict__ bhh)
{
    __shared__ float As[GBK][GBM];
    __shared__ float Bs[GBK][GBN];

    const int tid = threadIdx.x;
    const int m0 = blockIdx.y * GBM;
    const int n0 = blockIdx.x * GBN;

    const int lrow = tid >> 1;
    const int lk4  = (tid & 1) * 4;

    const int tx = tid & 15;   // n-block of 8 (4 pairs)
    const int ty = tid >> 4;   // m-block of 8

    unsigned long long acc2[8][4];
#pragma unroll
    for (int i = 0; i < 8; i++)
#pragma unroll
        for (int j2 = 0; j2 < 4; j2++) acc2[i][j2] = 0ull;

    const float* Aptr = x   + (size_t)(m0 + lrow) * ISZ + lk4;
    const float* Bptr = wih + (size_t)(n0 + lrow) * ISZ + lk4;

    float4 pa = *(const float4*)Aptr;
    float4 pb = *(const float4*)Bptr;

    const int NTK = ISZ / GBK;
    for (int t = 0; t < NTK; t++) {
        As[lk4 + 0][lrow] = pa.x; As[lk4 + 1][lrow] = pa.y;
        As[lk4 + 2][lrow] = pa.z; As[lk4 + 3][lrow] = pa.w;
        Bs[lk4 + 0][lrow] = pb.x; Bs[lk4 + 1][lrow] = pb.y;
        Bs[lk4 + 2][lrow] = pb.z; Bs[lk4 + 3][lrow] = pb.w;
        __syncthreads();

        if (t + 1 < NTK) {
            pa = *(const float4*)(Aptr + (t + 1) * GBK);
            pb = *(const float4*)(Bptr + (t + 1) * GBK);
        }

#pragma unroll
        for (int kk = 0; kk < GBK; kk++) {
            unsigned long long a2[8], b2[4];
#pragma unroll
            for (int i = 0; i < 8; i++) a2[i] = bcast2(As[kk][ty * 8 + i]);
#pragma unroll
            for (int j2 = 0; j2 < 4; j2++)
                b2[j2] = *(const unsigned long long*)&Bs[kk][tx * 8 + j2 * 2];
#pragma unroll
            for (int i = 0; i < 8; i++)
#pragma unroll
                for (int j2 = 0; j2 < 4; j2++)
                    fma2(acc2[i][j2], a2[i], b2[j2]);
        }
        __syncthreads();
    }

    float bsum[8];
#pragma unroll
    for (int j = 0; j < 8; j++) {
        int n = n0 + tx * 8 + j;
        bsum[j] = bih[n] + bhh[n];
    }

#pragma unroll
    for (int i = 0; i < 8; i++) {
        int m = m0 + ty * 8 + i;
        int b = m >> 9;
        int s = m & 511;
        float* orow = g_xproj + ((size_t)s * BATCH + b) * GATES + n0 + tx * 8;
#pragma unroll
        for (int j2 = 0; j2 < 4; j2 += 2) {
            float2 f0 = unpack2(acc2[i][j2 + 0]);
            float2 f1 = unpack2(acc2[i][j2 + 1]);
            float4 v;
            v.x = f0.x + bsum[j2 * 2 + 0];
            v.y = f0.y + bsum[j2 * 2 + 1];
            v.z = f1.x + bsum[j2 * 2 + 2];
            v.w = f1.y + bsum[j2 * 2 + 3];
            *(float4*)(orow + j2 * 2) = v;
        }
    }
}

// ===========================================================================
// Kernel 2: persistent recurrence. 128 blocks (1/SM), 512 threads.
// Block bid owns hidden units j0..j0+3 (16 W_hh rows), all 64 batches.
// W_hh resident in smem for all 512 steps; c state in registers.
// Per step: stage h (transposed [k][b]) from global double buffer, packed
// f32x2 dot products, warp butterfly + smem reduce, fused cell update,
// software grid barrier.
// ===========================================================================
#define NB   128
#define NT   512
#define WSTR 520                 // padded W row stride (2080 B, 16B-aligned)
#define HTR  68                  // padded h row stride (272 B, 16B-aligned)
#define SMW  (16 * WSTR)         // 8320 floats
#define SMH  (HS * HTR)          // 34816 floats
#define SMRED (16 * 4 * 4 * 8)   // 2048 floats: [warp][jl][pi][g*2+el]
#define PERS_SMEM_BYTES ((SMW + SMH + SMRED) * 4)   // 180,736 B

__device__ __forceinline__ float fsigmoid(float x) {
    return 1.f / (1.f + __expf(-x));
}
__device__ __forceinline__ float ftanh_fast(float x) {
    return 2.f / (1.f + __expf(-2.f * x)) - 1.f;
}

__global__ __launch_bounds__(NT, 1)
void lstm_persistent_kernel(const float* __restrict__ whh,
                            float* __restrict__ out,
                            float* __restrict__ hf_out,
                            float* __restrict__ cf_out)
{
    extern __shared__ float sm[];
    float* W_s = sm;                 // [16][WSTR], row = g*4 + jl
    float* h_s = sm + SMW;           // [512][HTR], [k][b]
    float* red = sm + SMW + SMH;     // [16][4][4][8]

    const int tid = threadIdx.x;
    const int j0 = blockIdx.x * 4;

    // ---- stage W_hh once for the whole sequence ----
    for (int t = tid; t < 16 * 128; t += NT) {
        int row = t >> 7;
        int kq = (t & 127) << 2;
        int g = row >> 2, jl = row & 3;
        float4 v = *(const float4*)(whh + (size_t)(g * HS + j0 + jl) * HS + kq);
        *(float4*)&W_s[row * WSTR + kq] = v;
    }
    __syncthreads();

    const int jl   = tid & 3;            // gate column within block
    const int ksub = (tid >> 2) & 15;    // k slice
    const int bg   = tid >> 6;           // batch group (8 batches)
    const int b0   = bg * 8;
    const int warp = tid >> 5;
    const int lane = tid & 31;

    // cell-update mapping (threads 0..255)
    const int ub = tid >> 2;             // batch
    const int uj = j0 + (tid & 3);       // hidden unit
    float c_reg = 0.f;

    for (int s = 0; s < SEQ; s++) {
        // prefetch x_proj values early (hides DRAM latency behind compute)
        float xp0 = 0.f, xp1 = 0.f, xp2 = 0.f, xp3 = 0.f;
        if (tid < 256) {
            const float* xp = g_xproj + ((size_t)s * BATCH + ub) * GATES;
            xp0 = xp[0 * HS + uj];
            xp1 = xp[1 * HS + uj];
            xp2 = xp[2 * HS + uj];
            xp3 = xp[3 * HS + uj];
        }

        float gsum[4] = {0.f, 0.f, 0.f, 0.f};

        if (s > 0) {
            // ---- stage h_{s-1}: g_h[(s-1)&1][k][b] -> h_s ----
            const float* hsrc = &g_h[(s + 1) & 1][0][0];
            for (int t = tid; t < (HS * BATCH) / 4; t += NT) {
                int k  = t >> 4;
                int c4 = (t & 15) << 2;
                float4 v = *(const float4*)(hsrc + k * BATCH + c4);
                *(float4*)&h_s[k * HTR + c4] = v;
            }
            __syncthreads();

            // ---- packed dot products: 4 gates x 8 batches (4 pairs) x 32 k ----
            unsigned long long acc[4][4];
#pragma unroll
            for (int pi = 0; pi < 4; pi++)
#pragma unroll
                for (int g = 0; g < 4; g++) acc[pi][g] = 0ull;

#pragma unroll 4
            for (int r = 0; r < 32; r++) {
                int k = ksub + (r << 4);
                unsigned long long w2[4];
#pragma unroll
                for (int g = 0; g < 4; g++)
                    w2[g] = bcast2(W_s[(g * 4 + jl) * WSTR + k]);
                const float* hrow = &h_s[k * HTR + b0];
#pragma unroll
                for (int pi = 0; pi < 4; pi++) {
                    unsigned long long h2 = *(const unsigned long long*)(hrow + pi * 2);
#pragma unroll
                    for (int g = 0; g < 4; g++) fma2(acc[pi][g], h2, w2[g]);
                }
            }

            // ---- butterfly over ksub low 3 bits (lane bits 2..4) ----
            float v[4][4][2];
#pragma unroll
            for (int pi = 0; pi < 4; pi++)
#pragma unroll
                for (int g = 0; g < 4; g++) {
                    float2 f = unpack2(acc[pi][g]);
                    v[pi][g][0] = f.x; v[pi][g][1] = f.y;
                }
#pragma unroll
            for (int off = 4; off <= 16; off <<= 1) {
#pragma unroll
                for (int pi = 0; pi < 4; pi++)
#pragma unroll
                    for (int g = 0; g < 4; g++) {
                        v[pi][g][0] += __shfl_xor_sync(0xffffffffu, v[pi][g][0], off);
                        v[pi][g][1] += __shfl_xor_sync(0xffffffffu, v[pi][g][1], off);
                    }
            }
            if (lane < 4) {   // lane == jl representative
#pragma unroll
                for (int pi = 0; pi < 4; pi++)
#pragma unroll
                    for (int g = 0; g < 4; g++) {
                        red[((warp * 4 + lane) * 4 + pi) * 8 + g * 2 + 0] = v[pi][g][0];
                        red[((warp * 4 + lane) * 4 + pi) * 8 + g * 2 + 1] = v[pi][g][1];
                    }
            }
            __syncthreads();

            if (tid < 256) {
                int cbg = ub >> 3;
                int cpi = (ub & 7) >> 1;
                int cel = ub & 1;
                int cjl = tid & 3;
                int w0 = cbg * 2, w1 = cbg * 2 + 1;
#pragma unroll
                for (int g = 0; g < 4; g++)
                    gsum[g] = red[((w0 * 4 + cjl) * 4 + cpi) * 8 + g * 2 + cel]
                            + red[((w1 * 4 + cjl) * 4 + cpi) * 8 + g * 2 + cel];
            }
        }

        // ---- cell update ----
        if (tid < 256) {
            float gi = gsum[0] + xp0;
            float gf = gsum[1] + xp1;
            float gc = gsum[2] + xp2;
            float go = gsum[3] + xp3;

            float i_ = fsigmoid(gi);
            float f_ = fsigmoid(gf);
            float g_ = ftanh_fast(gc);
            float o_ = fsigmoid(go);

            float cn = f_ * c_reg + i_ * g_;
            float hn = o_ * ftanh_fast(cn);
            c_reg = cn;

            out[((size_t)ub * SEQ + s) * HS + uj] = hn;
            g_h[s & 1][uj][ub] = hn;
            if (s == SEQ - 1 && hf_out != nullptr) {
                hf_out[ub * HS + uj] = hn;
                cf_out[ub * HS + uj] = cn;
            }
        }

        // ---- grid barrier (epoch s+1) ----
        __syncthreads();
        if (tid == 0) {
            __threadfence();
            unsigned prev = atomicAdd(&g_count, 1u);
            unsigned target = (unsigned)(s + 1);
            if (prev == target * NB - 1u) {
                atomicExch(&g_release, target);   // release: fenced by arrivals above
            } else {
                unsigned r;
                do {
                    asm volatile("ld.acquire.gpu.u32 %0, [%1];" : "=r"(r) : "l"(&g_release));
                } while (r < target);
            }
        }
        __syncthreads();
    }
}

// ===========================================================================
// Launch
// ===========================================================================
extern "C" void kernel_launch(void* const* d_in, const int* in_sizes, int n_in,
                              void* d_out, int out_size)
{
    const float* x   = (const float*)d_in[0];
    const float* wih = (const float*)d_in[1];
    const float* whh = (const float*)d_in[2];
    const float* bih = (const float*)d_in[3];
    const float* bhh = (const float*)d_in[4];

    float* out = (float*)d_out;

    const size_t hidden_elems = (size_t)BATCH * SEQ * HS;
    float* hf = nullptr;
    float* cf = nullptr;
    if ((size_t)out_size >= hidden_elems + 2 * (size_t)BATCH * HS) {
        hf = out + hidden_elems;
        cf = hf + (size_t)BATCH * HS;
    }

    cudaFuncSetAttribute(lstm_persistent_kernel,
                         cudaFuncAttributeMaxDynamicSharedMemorySize,
                         PERS_SMEM_BYTES);

    // reset grid-barrier state (every replay)
    init_barrier_kernel<<<1, 1>>>();

    // Phase 1: input projection GEMM
    dim3 ggrid(GATES / GBN, (BATCH * SEQ) / GBM);
    xproj_gemm_kernel<<<ggrid, 256>>>(x, wih, bih, bhh);

    // Phase 2: persistent recurrence (single launch, internal grid barriers)
    lstm_persistent_kernel<<<NB, NT, PERS_SMEM_BYTES>>>(whh, out, hf, cf);
}